// round 4
// baseline (speedup 1.0000x reference)
#include <cuda_runtime.h>
#include <cstddef>

// ---------------------------------------------------------------------------
// HyperNet fused pipeline.
//
// Algebra: z = client_enc @ Wtop + mean_update @ Wbot + comb_b
//            = reluA @ (enc_w2 @ Wtop)  +  h2 @ (pol_w3 @ Wbot)
//              + (pol_b3 @ Wbot + comb_b)
// so we fold weights once per launch (K0), build Acat = [reluA | h2] (K1),
// and run one skinny [N,96]@[96,1024] GEMM + distribution epilogue (K2).
// ---------------------------------------------------------------------------

#define NC     16384      // n_clients
#define IN_DIM 512
#define P_DIM  1024
#define H_ENC  64
#define H_POL  32
#define F_DIM  96         // 64 + 32

// scratch (device globals — no allocation allowed)
__device__ float g_Wcat[(F_DIM + 1) * P_DIM];   // rows 0..63 enc, 64..95 pol, 96 bias
__device__ float g_Acat[F_DIM * NC];            // transposed: [feature][client]

// constants
#define SQRT_VAR      0.22360679774997896f
#define LOGPROB_CONST 592.8218660580586f        // -0.5*1024*(log2pi + log(0.05))
#define ENTROPY_CONST -80.82186605805859f       // 0.5*1024*(log2pi + log(0.05) + 1)

// ---- f32x2 helpers (packed fp32 FMA, sm_103a) -----------------------------
__device__ __forceinline__ unsigned long long pack2(float lo, float hi) {
    unsigned long long r;
    asm("mov.b64 %0, {%1, %2};" : "=l"(r) : "f"(lo), "f"(hi));
    return r;
}
__device__ __forceinline__ float2 unpack2(unsigned long long v) {
    float2 r;
    asm("mov.b64 {%0, %1}, %2;" : "=f"(r.x), "=f"(r.y) : "l"(v));
    return r;
}
__device__ __forceinline__ void fma2(unsigned long long& d,
                                     unsigned long long a,
                                     unsigned long long b) {
    asm("fma.rn.f32x2 %0, %1, %2, %0;" : "+l"(d) : "l"(a), "l"(b));
}

// ---------------------------------------------------------------------------
// K0: fold weights.  g_Wcat[r][j]:
//   r <  64 : sum_p enc_w2[r][p]  * comb_w[p][j]
//   r <  96 : sum_p pol_w3[r-64][p] * comb_w[1024+p][j]
//   r == 96 : sum_p pol_b3[p] * comb_w[1024+p][j] + comb_b[j]
// grid (8, 25), block 128. Each CTA: 4 rows x 128 cols, K = 1024.
// ---------------------------------------------------------------------------
__global__ void __launch_bounds__(128) k0_fold(
    const float* __restrict__ enc_w2, const float* __restrict__ pol_w3,
    const float* __restrict__ pol_b3, const float* __restrict__ comb_w,
    const float* __restrict__ comb_b)
{
    const int j  = blockIdx.x * 128 + threadIdx.x;
    const int r0 = blockIdx.y * 4;
    const float* cw = comb_w + (size_t)((r0 < 64) ? 0 : P_DIM * P_DIM) + j;

    const float* v[4];
#pragma unroll
    for (int i = 0; i < 4; i++) {
        int r = r0 + i;
        if (r > F_DIM) r = F_DIM;
        v[i] = (r < 64) ? (enc_w2 + (size_t)r * P_DIM)
             : (r < 96) ? (pol_w3 + (size_t)(r - 64) * P_DIM)
                        : pol_b3;
    }

    float acc[4] = {0.f, 0.f, 0.f, 0.f};
#pragma unroll 8
    for (int p = 0; p < P_DIM; p++) {
        const float c = cw[(size_t)p * P_DIM];
#pragma unroll
        for (int i = 0; i < 4; i++) acc[i] += v[i][p] * c;
    }

#pragma unroll
    for (int i = 0; i < 4; i++) {
        const int r = r0 + i;
        if (r < F_DIM) {
            g_Wcat[r * P_DIM + j] = acc[i];
        } else if (r == F_DIM) {
            g_Wcat[F_DIM * P_DIM + j] = acc[i] + comb_b[j];
        }
    }
}

// ---------------------------------------------------------------------------
// K1: Acat = [ relu(enc @ enc_w1) | relu(relu(mean@pw1+b1)@pw2+b2) ]
// One CTA = 32 clients, 256 threads. Tiles staged in smem (contiguous copies),
// scalar FFMA with 8-deep weight prefetch. Output written transposed.
// ---------------------------------------------------------------------------
#define K1_SMEM_FLOATS (32*IN_DIM + 32*P_DIM + 32*H_POL + F_DIM*33)
#define K1_SMEM_BYTES  (K1_SMEM_FLOATS * 4)

__global__ void __launch_bounds__(256) k1_acat(
    const float* __restrict__ enc, const float* __restrict__ mean,
    const float* __restrict__ w1,  const float* __restrict__ pw1,
    const float* __restrict__ pb1, const float* __restrict__ pw2,
    const float* __restrict__ pb2)
{
    extern __shared__ float sm[];
    float* enc_s  = sm;                                  // [32][512]
    float* mean_s = sm + 32 * IN_DIM;                    // [32][1024]
    float* h1_s   = mean_s + 32 * P_DIM;                 // [32][32]
    float* acat   = h1_s + 32 * H_POL;                   // [96][33]

    const int tid  = threadIdx.x;
    const int base = blockIdx.x * 32;

    // --- stage tiles (rows are consecutive clients -> fully contiguous) ---
    {
        const float4* src = (const float4*)(enc + (size_t)base * IN_DIM);
        float4* dst = (float4*)enc_s;
        for (int i = tid; i < 32 * (IN_DIM / 4); i += 256) dst[i] = src[i];
    }
    {
        const float4* src = (const float4*)(mean + (size_t)base * P_DIM);
        float4* dst = (float4*)mean_s;
        for (int i = tid; i < 32 * (P_DIM / 4); i += 256) dst[i] = src[i];
    }
    __syncthreads();

    // --- enc GEMM: A[32][64] = relu(enc_tile @ w1), K=512 ---
    {
        const int h = tid & 63;           // output column
        const int g = tid >> 6;           // row group (8 rows each)
        const float* es = enc_s + (size_t)g * 8 * IN_DIM;
        const float* wp = w1 + h;

        float acc[8];
#pragma unroll
        for (int r = 0; r < 8; r++) acc[r] = 0.f;

        float wb[8];
#pragma unroll
        for (int t = 0; t < 8; t++) wb[t] = wp[t * H_ENC];

        for (int kk = 0; kk < IN_DIM; kk += 8) {
            float wn[8];
            const int nb = (kk + 8 < IN_DIM) ? (kk + 8) : kk;
#pragma unroll
            for (int t = 0; t < 8; t++) wn[t] = wp[(nb + t) * H_ENC];
#pragma unroll
            for (int t = 0; t < 8; t++) {
                const float w = wb[t];
                const float* e = es + kk + t;
#pragma unroll
                for (int r = 0; r < 8; r++) acc[r] += e[r * IN_DIM] * w;
            }
#pragma unroll
            for (int t = 0; t < 8; t++) wb[t] = wn[t];
        }
#pragma unroll
        for (int r = 0; r < 8; r++)
            acat[h * 33 + g * 8 + r] = fmaxf(acc[r], 0.f);
    }

    // --- pol GEMM 1: h1[32][32] = relu(mean_tile @ pw1 + b1), K=1024 ---
    const int hc = tid & 31;
    const int g2 = tid >> 5;              // 8 groups x 4 rows
    {
        const float* ms = mean_s + (size_t)g2 * 4 * P_DIM;
        const float* wp = pw1 + hc;

        float acc[4] = {0.f, 0.f, 0.f, 0.f};
        float wb[8];
#pragma unroll
        for (int t = 0; t < 8; t++) wb[t] = wp[t * H_POL];

        for (int kk = 0; kk < P_DIM; kk += 8) {
            float wn[8];
            const int nb = (kk + 8 < P_DIM) ? (kk + 8) : kk;
#pragma unroll
            for (int t = 0; t < 8; t++) wn[t] = wp[(nb + t) * H_POL];
#pragma unroll
            for (int t = 0; t < 8; t++) {
                const float w = wb[t];
                const float* m = ms + kk + t;
#pragma unroll
                for (int r = 0; r < 4; r++) acc[r] += m[r * P_DIM] * w;
            }
#pragma unroll
            for (int t = 0; t < 8; t++) wb[t] = wn[t];
        }
        const float b = pb1[hc];
#pragma unroll
        for (int r = 0; r < 4; r++)
            h1_s[(g2 * 4 + r) * H_POL + hc] = fmaxf(acc[r] + b, 0.f);
    }
    __syncthreads();

    // --- pol GEMM 2: h2 = relu(h1 @ pw2 + b2), K=32 (weights L1-resident) ---
    {
        float acc[4] = {0.f, 0.f, 0.f, 0.f};
#pragma unroll
        for (int k = 0; k < H_POL; k++) {
            const float w = pw2[k * H_POL + hc];
#pragma unroll
            for (int r = 0; r < 4; r++)
                acc[r] += h1_s[(g2 * 4 + r) * H_POL + k] * w;
        }
        const float b = pb2[hc];
#pragma unroll
        for (int r = 0; r < 4; r++)
            acat[(64 + hc) * 33 + g2 * 4 + r] = fmaxf(acc[r] + b, 0.f);
    }
    __syncthreads();

    // --- write Acat transposed: g_Acat[feature][client] (coalesced) ---
    for (int i = tid; i < F_DIM * 32; i += 256) {
        const int r = i >> 5;
        const int m = i & 31;
        g_Acat[(size_t)r * NC + base + m] = acat[r * 33 + m];
    }
}

// ---------------------------------------------------------------------------
// K2: z[N][1024] = Acat @ Wcat + bias row, then sigmoid / sample / clip /
// logprob / entropy epilogue. f32x2 packed FMAs over client row-pairs.
// One CTA = 16 clients x 1024 cols, 256 threads (4 cols each).
// ---------------------------------------------------------------------------
__global__ void __launch_bounds__(256, 2) k2_final(
    const float* __restrict__ eps,
    float* __restrict__ out_sample,
    float* __restrict__ out_logprob,
    float* __restrict__ out_entropy)
{
    __shared__ float aT[F_DIM * 16];   // [96][16]; reused as reduction buffer

    const int tid = threadIdx.x;
    const int m0  = blockIdx.x * 16;

    for (int i = tid; i < F_DIM * 16; i += 256) {
        const int r = i >> 4;
        const int m = i & 15;
        aT[i] = g_Acat[(size_t)r * NC + m0 + m];
    }
    __syncthreads();

    const int j0 = tid * 4;

    unsigned long long acc[8][4];
#pragma unroll
    for (int mp = 0; mp < 8; mp++)
#pragma unroll
        for (int c = 0; c < 4; c++) acc[mp][c] = 0ull;

#pragma unroll 4
    for (int r = 0; r < F_DIM; r++) {
        const float4 w = *(const float4*)(g_Wcat + r * P_DIM + j0);
        const unsigned long long wd0 = pack2(w.x, w.x);
        const unsigned long long wd1 = pack2(w.y, w.y);
        const unsigned long long wd2 = pack2(w.z, w.z);
        const unsigned long long wd3 = pack2(w.w, w.w);
#pragma unroll
        for (int mp = 0; mp < 8; mp++) {
            const unsigned long long a2 =
                *(const unsigned long long*)(aT + r * 16 + 2 * mp);
            fma2(acc[mp][0], a2, wd0);
            fma2(acc[mp][1], a2, wd1);
            fma2(acc[mp][2], a2, wd2);
            fma2(acc[mp][3], a2, wd3);
        }
    }
    __syncthreads();   // before reusing aT as reduction scratch

    const float4 b4 = *(const float4*)(g_Wcat + F_DIM * P_DIM + j0);
    const int wid  = tid >> 5;
    const int lane = tid & 31;

#pragma unroll
    for (int mp = 0; mp < 8; mp++) {
        const float2 z0 = unpack2(acc[mp][0]);
        const float2 z1 = unpack2(acc[mp][1]);
        const float2 z2 = unpack2(acc[mp][2]);
        const float2 z3 = unpack2(acc[mp][3]);
#pragma unroll
        for (int hh = 0; hh < 2; hh++) {
            const int row = 2 * mp + hh;
            float z[4];
            z[0] = (hh ? z0.y : z0.x) + b4.x;
            z[1] = (hh ? z1.y : z1.x) + b4.y;
            z[2] = (hh ? z2.y : z2.x) + b4.z;
            z[3] = (hh ? z3.y : z3.x) + b4.w;

            const float4 e4 =
                *(const float4*)(eps + (size_t)(m0 + row) * P_DIM + j0);
            const float ev[4] = {e4.x, e4.y, e4.z, e4.w};

            float4 s4;
            float sv[4];
            float ss = 0.f;
#pragma unroll
            for (int c = 0; c < 4; c++) {
                const float mv = __fdividef(1.f, 1.f + __expf(-z[c]));
                float s = mv + SQRT_VAR * ev[c];
                s = fminf(fmaxf(s, 0.f), 1.f);
                const float d = s - mv;
                ss += d * d;
                sv[c] = s;
            }
            s4.x = sv[0]; s4.y = sv[1]; s4.z = sv[2]; s4.w = sv[3];
            *(float4*)(out_sample + (size_t)(m0 + row) * P_DIM + j0) = s4;

#pragma unroll
            for (int o = 16; o; o >>= 1)
                ss += __shfl_xor_sync(0xffffffffu, ss, o);
            if (lane == 0) aT[row * 8 + wid] = ss;
        }
    }
    __syncthreads();

    if (tid < 16) {
        float s = 0.f;
#pragma unroll
        for (int w = 0; w < 8; w++) s += aT[tid * 8 + w];
        out_logprob[m0 + tid] = -10.0f * s + LOGPROB_CONST;   // -0.5/VAR = -10
        out_entropy[m0 + tid] = ENTROPY_CONST;
    }
}

// ---------------------------------------------------------------------------
extern "C" void kernel_launch(void* const* d_in, const int* in_sizes, int n_in,
                              void* d_out, int out_size) {
    const float* encoding = (const float*)d_in[0];
    const float* mean     = (const float*)d_in[1];
    const float* enc_w1   = (const float*)d_in[2];
    const float* enc_w2   = (const float*)d_in[3];
    const float* pol_w1   = (const float*)d_in[4];
    const float* pol_b1   = (const float*)d_in[5];
    const float* pol_w2   = (const float*)d_in[6];
    const float* pol_b2   = (const float*)d_in[7];
    const float* pol_w3   = (const float*)d_in[8];
    const float* pol_b3   = (const float*)d_in[9];
    const float* comb_w   = (const float*)d_in[10];
    const float* comb_b   = (const float*)d_in[11];
    const float* eps      = (const float*)d_in[12];

    float* out         = (float*)d_out;
    float* out_sample  = out;                                   // [N, 1024]
    float* out_logprob = out + (size_t)NC * P_DIM;              // [N]
    float* out_entropy = out_logprob + NC;                      // [N]

    cudaFuncSetAttribute(k1_acat,
                         cudaFuncAttributeMaxDynamicSharedMemorySize,
                         K1_SMEM_BYTES);

    k0_fold<<<dim3(8, 25), 128>>>(enc_w2, pol_w3, pol_b3, comb_w, comb_b);
    k1_acat<<<NC / 32, 256, K1_SMEM_BYTES>>>(encoding, mean, enc_w1,
                                             pol_w1, pol_b1, pol_w2, pol_b2);
    k2_final<<<NC / 16, 256>>>(eps, out_sample, out_logprob, out_entropy);
}

// round 5
// speedup vs baseline: 1.0013x; 1.0013x over previous
#include <cuda_runtime.h>
#include <cstddef>

// ---------------------------------------------------------------------------
// HyperNet fused pipeline.
//
// Algebra: z = client_enc @ Wtop + mean_update @ Wbot + comb_b
//            = reluA @ (enc_w2 @ Wtop)  +  h2 @ (pol_w3 @ Wbot)
//              + (pol_b3 @ Wbot + comb_b)
// so we fold weights once per launch (K0), build Acat = [reluA | h2] (K1),
// and run one skinny [N,96]@[96,1024] GEMM + distribution epilogue (K2).
// ---------------------------------------------------------------------------

#define NC     16384      // n_clients
#define IN_DIM 512
#define P_DIM  1024
#define H_ENC  64
#define H_POL  32
#define F_DIM  96         // 64 + 32

// scratch (device globals — no allocation allowed)
__device__ float g_Wcat[(F_DIM + 1) * P_DIM];   // rows 0..63 enc, 64..95 pol, 96 bias
__device__ float g_Acat[F_DIM * NC];            // transposed: [feature][client]

// constants
#define SQRT_VAR      0.22360679774997896f
#define LOGPROB_CONST 592.8218660580586f        // -0.5*1024*(log2pi + log(0.05))
#define ENTROPY_CONST -80.82186605805859f       // 0.5*1024*(log2pi + log(0.05) + 1)

// ---- f32x2 helpers (packed fp32 FMA, sm_103a) -----------------------------
__device__ __forceinline__ unsigned long long pack2(float lo, float hi) {
    unsigned long long r;
    asm("mov.b64 %0, {%1, %2};" : "=l"(r) : "f"(lo), "f"(hi));
    return r;
}
__device__ __forceinline__ float2 unpack2(unsigned long long v) {
    float2 r;
    asm("mov.b64 {%0, %1}, %2;" : "=f"(r.x), "=f"(r.y) : "l"(v));
    return r;
}
__device__ __forceinline__ void fma2(unsigned long long& d,
                                     unsigned long long a,
                                     unsigned long long b) {
    asm("fma.rn.f32x2 %0, %1, %2, %0;" : "+l"(d) : "l"(a), "l"(b));
}

// ---------------------------------------------------------------------------
// K0: fold weights.  g_Wcat[r][j]:
//   r <  64 : sum_p enc_w2[r][p]  * comb_w[p][j]
//   r <  96 : sum_p pol_w3[r-64][p] * comb_w[1024+p][j]
//   r == 96 : sum_p pol_b3[p] * comb_w[1024+p][j] + comb_b[j]
// grid (8, 25), block 128. Each CTA: 4 rows x 128 cols, K = 1024.
// ---------------------------------------------------------------------------
__global__ void __launch_bounds__(128) k0_fold(
    const float* __restrict__ enc_w2, const float* __restrict__ pol_w3,
    const float* __restrict__ pol_b3, const float* __restrict__ comb_w,
    const float* __restrict__ comb_b)
{
    const int j  = blockIdx.x * 128 + threadIdx.x;
    const int r0 = blockIdx.y * 4;
    const float* cw = comb_w + (size_t)((r0 < 64) ? 0 : P_DIM * P_DIM) + j;

    const float* v[4];
#pragma unroll
    for (int i = 0; i < 4; i++) {
        int r = r0 + i;
        if (r > F_DIM) r = F_DIM;
        v[i] = (r < 64) ? (enc_w2 + (size_t)r * P_DIM)
             : (r < 96) ? (pol_w3 + (size_t)(r - 64) * P_DIM)
                        : pol_b3;
    }

    float acc[4] = {0.f, 0.f, 0.f, 0.f};
#pragma unroll 8
    for (int p = 0; p < P_DIM; p++) {
        const float c = cw[(size_t)p * P_DIM];
#pragma unroll
        for (int i = 0; i < 4; i++) acc[i] += v[i][p] * c;
    }

#pragma unroll
    for (int i = 0; i < 4; i++) {
        const int r = r0 + i;
        if (r < F_DIM) {
            g_Wcat[r * P_DIM + j] = acc[i];
        } else if (r == F_DIM) {
            g_Wcat[F_DIM * P_DIM + j] = acc[i] + comb_b[j];
        }
    }
}

// ---------------------------------------------------------------------------
// K1: Acat = [ relu(enc @ enc_w1) | relu(relu(mean@pw1+b1)@pw2+b2) ]
// One CTA = 32 clients, 256 threads. Tiles staged in smem (contiguous copies),
// scalar FFMA with 8-deep weight prefetch. Output written transposed.
// ---------------------------------------------------------------------------
#define K1_SMEM_FLOATS (32*IN_DIM + 32*P_DIM + 32*H_POL + F_DIM*33)
#define K1_SMEM_BYTES  (K1_SMEM_FLOATS * 4)

__global__ void __launch_bounds__(256) k1_acat(
    const float* __restrict__ enc, const float* __restrict__ mean,
    const float* __restrict__ w1,  const float* __restrict__ pw1,
    const float* __restrict__ pb1, const float* __restrict__ pw2,
    const float* __restrict__ pb2)
{
    extern __shared__ float sm[];
    float* enc_s  = sm;                                  // [32][512]
    float* mean_s = sm + 32 * IN_DIM;                    // [32][1024]
    float* h1_s   = mean_s + 32 * P_DIM;                 // [32][32]
    float* acat   = h1_s + 32 * H_POL;                   // [96][33]

    const int tid  = threadIdx.x;
    const int base = blockIdx.x * 32;

    // --- stage tiles (rows are consecutive clients -> fully contiguous) ---
    {
        const float4* src = (const float4*)(enc + (size_t)base * IN_DIM);
        float4* dst = (float4*)enc_s;
        for (int i = tid; i < 32 * (IN_DIM / 4); i += 256) dst[i] = src[i];
    }
    {
        const float4* src = (const float4*)(mean + (size_t)base * P_DIM);
        float4* dst = (float4*)mean_s;
        for (int i = tid; i < 32 * (P_DIM / 4); i += 256) dst[i] = src[i];
    }
    __syncthreads();

    // --- enc GEMM: A[32][64] = relu(enc_tile @ w1), K=512 ---
    {
        const int h = tid & 63;           // output column
        const int g = tid >> 6;           // row group (8 rows each)
        const float* es = enc_s + (size_t)g * 8 * IN_DIM;
        const float* wp = w1 + h;

        float acc[8];
#pragma unroll
        for (int r = 0; r < 8; r++) acc[r] = 0.f;

        float wb[8];
#pragma unroll
        for (int t = 0; t < 8; t++) wb[t] = wp[t * H_ENC];

        for (int kk = 0; kk < IN_DIM; kk += 8) {
            float wn[8];
            const int nb = (kk + 8 < IN_DIM) ? (kk + 8) : kk;
#pragma unroll
            for (int t = 0; t < 8; t++) wn[t] = wp[(nb + t) * H_ENC];
#pragma unroll
            for (int t = 0; t < 8; t++) {
                const float w = wb[t];
                const float* e = es + kk + t;
#pragma unroll
                for (int r = 0; r < 8; r++) acc[r] += e[r * IN_DIM] * w;
            }
#pragma unroll
            for (int t = 0; t < 8; t++) wb[t] = wn[t];
        }
#pragma unroll
        for (int r = 0; r < 8; r++)
            acat[h * 33 + g * 8 + r] = fmaxf(acc[r], 0.f);
    }

    // --- pol GEMM 1: h1[32][32] = relu(mean_tile @ pw1 + b1), K=1024 ---
    const int hc = tid & 31;
    const int g2 = tid >> 5;              // 8 groups x 4 rows
    {
        const float* ms = mean_s + (size_t)g2 * 4 * P_DIM;
        const float* wp = pw1 + hc;

        float acc[4] = {0.f, 0.f, 0.f, 0.f};
        float wb[8];
#pragma unroll
        for (int t = 0; t < 8; t++) wb[t] = wp[t * H_POL];

        for (int kk = 0; kk < P_DIM; kk += 8) {
            float wn[8];
            const int nb = (kk + 8 < P_DIM) ? (kk + 8) : kk;
#pragma unroll
            for (int t = 0; t < 8; t++) wn[t] = wp[(nb + t) * H_POL];
#pragma unroll
            for (int t = 0; t < 8; t++) {
                const float w = wb[t];
                const float* m = ms + kk + t;
#pragma unroll
                for (int r = 0; r < 4; r++) acc[r] += m[r * P_DIM] * w;
            }
#pragma unroll
            for (int t = 0; t < 8; t++) wb[t] = wn[t];
        }
        const float b = pb1[hc];
#pragma unroll
        for (int r = 0; r < 4; r++)
            h1_s[(g2 * 4 + r) * H_POL + hc] = fmaxf(acc[r] + b, 0.f);
    }
    __syncthreads();

    // --- pol GEMM 2: h2 = relu(h1 @ pw2 + b2), K=32 (weights L1-resident) ---
    {
        float acc[4] = {0.f, 0.f, 0.f, 0.f};
#pragma unroll
        for (int k = 0; k < H_POL; k++) {
            const float w = pw2[k * H_POL + hc];
#pragma unroll
            for (int r = 0; r < 4; r++)
                acc[r] += h1_s[(g2 * 4 + r) * H_POL + k] * w;
        }
        const float b = pb2[hc];
#pragma unroll
        for (int r = 0; r < 4; r++)
            acat[(64 + hc) * 33 + g2 * 4 + r] = fmaxf(acc[r] + b, 0.f);
    }
    __syncthreads();

    // --- write Acat transposed: g_Acat[feature][client] (coalesced) ---
    for (int i = tid; i < F_DIM * 32; i += 256) {
        const int r = i >> 5;
        const int m = i & 31;
        g_Acat[(size_t)r * NC + base + m] = acat[r * 33 + m];
    }
}

// ---------------------------------------------------------------------------
// K2: z[N][1024] = Acat @ Wcat + bias row, then sigmoid / sample / clip /
// logprob / entropy epilogue. f32x2 packed FMAs over client row-pairs.
// One CTA = 16 clients x 1024 cols, 256 threads (4 cols each).
// ---------------------------------------------------------------------------
__global__ void __launch_bounds__(256, 2) k2_final(
    const float* __restrict__ eps,
    float* __restrict__ out_sample,
    float* __restrict__ out_logprob,
    float* __restrict__ out_entropy)
{
    __shared__ float aT[F_DIM * 16];   // [96][16]; reused as reduction buffer

    const int tid = threadIdx.x;
    const int m0  = blockIdx.x * 16;

    for (int i = tid; i < F_DIM * 16; i += 256) {
        const int r = i >> 4;
        const int m = i & 15;
        aT[i] = g_Acat[(size_t)r * NC + m0 + m];
    }
    __syncthreads();

    const int j0 = tid * 4;

    unsigned long long acc[8][4];
#pragma unroll
    for (int mp = 0; mp < 8; mp++)
#pragma unroll
        for (int c = 0; c < 4; c++) acc[mp][c] = 0ull;

#pragma unroll 4
    for (int r = 0; r < F_DIM; r++) {
        const float4 w = *(const float4*)(g_Wcat + r * P_DIM + j0);
        const unsigned long long wd0 = pack2(w.x, w.x);
        const unsigned long long wd1 = pack2(w.y, w.y);
        const unsigned long long wd2 = pack2(w.z, w.z);
        const unsigned long long wd3 = pack2(w.w, w.w);
#pragma unroll
        for (int mp = 0; mp < 8; mp++) {
            const unsigned long long a2 =
                *(const unsigned long long*)(aT + r * 16 + 2 * mp);
            fma2(acc[mp][0], a2, wd0);
            fma2(acc[mp][1], a2, wd1);
            fma2(acc[mp][2], a2, wd2);
            fma2(acc[mp][3], a2, wd3);
        }
    }
    __syncthreads();   // before reusing aT as reduction scratch

    const float4 b4 = *(const float4*)(g_Wcat + F_DIM * P_DIM + j0);
    const int wid  = tid >> 5;
    const int lane = tid & 31;

#pragma unroll
    for (int mp = 0; mp < 8; mp++) {
        const float2 z0 = unpack2(acc[mp][0]);
        const float2 z1 = unpack2(acc[mp][1]);
        const float2 z2 = unpack2(acc[mp][2]);
        const float2 z3 = unpack2(acc[mp][3]);
#pragma unroll
        for (int hh = 0; hh < 2; hh++) {
            const int row = 2 * mp + hh;
            float z[4];
            z[0] = (hh ? z0.y : z0.x) + b4.x;
            z[1] = (hh ? z1.y : z1.x) + b4.y;
            z[2] = (hh ? z2.y : z2.x) + b4.z;
            z[3] = (hh ? z3.y : z3.x) + b4.w;

            const float4 e4 =
                *(const float4*)(eps + (size_t)(m0 + row) * P_DIM + j0);
            const float ev[4] = {e4.x, e4.y, e4.z, e4.w};

            float4 s4;
            float sv[4];
            float ss = 0.f;
#pragma unroll
            for (int c = 0; c < 4; c++) {
                const float mv = __fdividef(1.f, 1.f + __expf(-z[c]));
                float s = mv + SQRT_VAR * ev[c];
                s = fminf(fmaxf(s, 0.f), 1.f);
                const float d = s - mv;
                ss += d * d;
                sv[c] = s;
            }
            s4.x = sv[0]; s4.y = sv[1]; s4.z = sv[2]; s4.w = sv[3];
            *(float4*)(out_sample + (size_t)(m0 + row) * P_DIM + j0) = s4;

#pragma unroll
            for (int o = 16; o; o >>= 1)
                ss += __shfl_xor_sync(0xffffffffu, ss, o);
            if (lane == 0) aT[row * 8 + wid] = ss;
        }
    }
    __syncthreads();

    if (tid < 16) {
        float s = 0.f;
#pragma unroll
        for (int w = 0; w < 8; w++) s += aT[tid * 8 + w];
        out_logprob[m0 + tid] = -10.0f * s + LOGPROB_CONST;   // -0.5/VAR = -10
        out_entropy[m0 + tid] = ENTROPY_CONST;
    }
}

// ---------------------------------------------------------------------------
extern "C" void kernel_launch(void* const* d_in, const int* in_sizes, int n_in,
                              void* d_out, int out_size) {
    const float* encoding = (const float*)d_in[0];
    const float* mean     = (const float*)d_in[1];
    const float* enc_w1   = (const float*)d_in[2];
    const float* enc_w2   = (const float*)d_in[3];
    const float* pol_w1   = (const float*)d_in[4];
    const float* pol_b1   = (const float*)d_in[5];
    const float* pol_w2   = (const float*)d_in[6];
    const float* pol_b2   = (const float*)d_in[7];
    const float* pol_w3   = (const float*)d_in[8];
    const float* pol_b3   = (const float*)d_in[9];
    const float* comb_w   = (const float*)d_in[10];
    const float* comb_b   = (const float*)d_in[11];
    const float* eps      = (const float*)d_in[12];

    float* out         = (float*)d_out;
    float* out_sample  = out;                                   // [N, 1024]
    float* out_logprob = out + (size_t)NC * P_DIM;              // [N]
    float* out_entropy = out_logprob + NC;                      // [N]

    cudaFuncSetAttribute(k1_acat,
                         cudaFuncAttributeMaxDynamicSharedMemorySize,
                         K1_SMEM_BYTES);

    k0_fold<<<dim3(8, 25), 128>>>(enc_w2, pol_w3, pol_b3, comb_w, comb_b);
    k1_acat<<<NC / 32, 256, K1_SMEM_BYTES>>>(encoding, mean, enc_w1,
                                             pol_w1, pol_b1, pol_w2, pol_b2);
    k2_final<<<NC / 16, 256>>>(eps, out_sample, out_logprob, out_entropy);
}

// round 6
// speedup vs baseline: 2.5170x; 2.5138x over previous
#include <cuda_runtime.h>
#include <cstddef>

// ---------------------------------------------------------------------------
// HyperNet fused pipeline (R6).
//   K0: fold weights -> g_Wcat[97][1024]   (row 96 = fused bias)
//   K1: Acat = [relu(enc@W1) | pol-MLP(mean)]  -> g_Acat[96][NC] (transposed)
//   K2: z = Acat @ Wcat + bias, sigmoid/sample/clip/logprob/entropy epilogue
// ---------------------------------------------------------------------------

#define NC     16384
#define IN_DIM 512
#define P_DIM  1024
#define H_ENC  64
#define H_POL  32
#define F_DIM  96

__device__ float g_Wcat[(F_DIM + 1) * P_DIM];
__device__ float g_Acat[F_DIM * NC];

#define SQRT_VAR      0.22360679774997896f
#define LOGPROB_CONST 592.8218660580586f
#define ENTROPY_CONST -80.82186605805859f

// ---- f32x2 helpers --------------------------------------------------------
__device__ __forceinline__ unsigned long long pack2(float lo, float hi) {
    unsigned long long r;
    asm("mov.b64 %0, {%1, %2};" : "=l"(r) : "f"(lo), "f"(hi));
    return r;
}
__device__ __forceinline__ float2 unpack2(unsigned long long v) {
    float2 r;
    asm("mov.b64 {%0, %1}, %2;" : "=f"(r.x), "=f"(r.y) : "l"(v));
    return r;
}
__device__ __forceinline__ void fma2(unsigned long long& d,
                                     unsigned long long a,
                                     unsigned long long b) {
    asm("fma.rn.f32x2 %0, %1, %2, %0;" : "+l"(d) : "l"(a), "l"(b));
}

// ---- cp.async helpers -----------------------------------------------------
__device__ __forceinline__ void cp16(void* s, const void* g) {
    unsigned sa = (unsigned)__cvta_generic_to_shared(s);
    asm volatile("cp.async.cg.shared.global [%0], [%1], 16;" :: "r"(sa), "l"(g));
}
#define CP_COMMIT() asm volatile("cp.async.commit_group;")
#define CP_WAIT1()  asm volatile("cp.async.wait_group 1;")
#define CP_WAIT0()  asm volatile("cp.async.wait_group 0;")

// ---------------------------------------------------------------------------
// K0 v2: latency-tolerant weight fold. grid (8, 13), block 128.
// Each CTA: 8 rows x 128 cols, K=1024. v rows staged in smem; comb_w column
// values streamed 16-deep (MLP 16) so the ~260cyc L2 latency is overlapped
// by the 8-row FMA + LDS work of each batch.
// ---------------------------------------------------------------------------
__global__ void __launch_bounds__(128) k0_fold(
    const float* __restrict__ enc_w2, const float* __restrict__ pol_w3,
    const float* __restrict__ pol_b3, const float* __restrict__ comb_w,
    const float* __restrict__ comb_b)
{
    __shared__ float vs[8 * P_DIM];          // 32 KB
    const int tid = threadIdx.x;
    const int r0  = blockIdx.y * 8;
    const int j   = blockIdx.x * 128 + tid;

    // stage 8 source rows (float4, coalesced)
#pragma unroll
    for (int t = 0; t < 16; t++) {
        const int i = tid + t * 128;         // float4 index 0..2047
        const int r = i >> 8, q = i & 255;
        int rr = r0 + r; if (rr > F_DIM) rr = F_DIM;
        const float* src = (rr < 64) ? (enc_w2 + (size_t)rr * P_DIM)
                         : (rr < 96) ? (pol_w3 + (size_t)(rr - 64) * P_DIM)
                                     : pol_b3;
        ((float4*)vs)[i] = ((const float4*)src)[q];
    }
    __syncthreads();

    const float* cw = comb_w + ((r0 >= 64) ? (size_t)P_DIM * P_DIM : 0) + j;

    float acc[8] = {0.f, 0.f, 0.f, 0.f, 0.f, 0.f, 0.f, 0.f};
#pragma unroll 1
    for (int p0 = 0; p0 < P_DIM; p0 += 16) {
        float c[16];
#pragma unroll
        for (int t = 0; t < 16; t++) c[t] = cw[(size_t)(p0 + t) * P_DIM];
#pragma unroll
        for (int t = 0; t < 16; t++) {
#pragma unroll
            for (int r = 0; r < 8; r++)
                acc[r] += vs[r * P_DIM + p0 + t] * c[t];
        }
    }

#pragma unroll
    for (int r = 0; r < 8; r++) {
        const int rr = r0 + r;
        if (rr < F_DIM)        g_Wcat[rr * P_DIM + j] = acc[r];
        else if (rr == F_DIM)  g_Wcat[F_DIM * P_DIM + j] = acc[r] + comb_b[j];
    }
}

// ---------------------------------------------------------------------------
// K1 v2: 32 clients/CTA, 256 threads, grid 512.
// Chunked (128-k) double-buffered cp.async staging of BOTH activations and
// weights; all inner loads are LDS (weights conflict-free, data broadcast,
// float4 over k). smem = 112.4 KB -> 2 CTAs/SM (16 warps).
// ---------------------------------------------------------------------------
#define K1_SW_OFF  8192                       // sD: [2][32*128]
#define K1_SH1_OFF (K1_SW_OFF + 16384)        // sW: [2][8192]
#define K1_SAC_OFF (K1_SH1_OFF + 1024)        // sH1: 32*32
#define K1_FLOATS  (K1_SAC_OFF + F_DIM * 33)  // sAc: 96*33
#define K1_BYTES   (K1_FLOATS * 4)

__global__ void __launch_bounds__(256) k1_acat(
    const float* __restrict__ enc, const float* __restrict__ mean,
    const float* __restrict__ w1,  const float* __restrict__ pw1,
    const float* __restrict__ pb1, const float* __restrict__ pw2,
    const float* __restrict__ pb2)
{
    extern __shared__ float sm[];
    float* sD  = sm;
    float* sW  = sm + K1_SW_OFF;
    float* sH1 = sm + K1_SH1_OFF;
    float* sAc = sm + K1_SAC_OFF;

    const int tid  = threadIdx.x;
    const int base = blockIdx.x * 32;

    auto stage_enc = [&](int ch, int b) {
        const float* eb = enc + (size_t)base * IN_DIM + ch * 128;
#pragma unroll
        for (int t = 0; t < 4; t++) {
            const int i = tid + t * 256, r = i >> 5, q = i & 31;
            cp16(sD + b * 4096 + r * 128 + q * 4,
                 eb + (size_t)r * IN_DIM + q * 4);
        }
        const float* wb = w1 + (size_t)(ch * 128) * H_ENC;
#pragma unroll
        for (int t = 0; t < 8; t++) {
            const int i = tid + t * 256, kk = i >> 4, q = i & 15;
            cp16(sW + b * 8192 + kk * 64 + q * 4,
                 wb + (size_t)kk * 64 + q * 4);
        }
        CP_COMMIT();
    };
    auto stage_pol = [&](int ch, int b) {
        const float* mb = mean + (size_t)base * P_DIM + ch * 128;
#pragma unroll
        for (int t = 0; t < 4; t++) {
            const int i = tid + t * 256, r = i >> 5, q = i & 31;
            cp16(sD + b * 4096 + r * 128 + q * 4,
                 mb + (size_t)r * P_DIM + q * 4);
        }
        const float* wb = pw1 + (size_t)(ch * 128) * H_POL;
#pragma unroll
        for (int t = 0; t < 4; t++) {
            const int i = tid + t * 256, kk = i >> 3, q = i & 7;
            cp16(sW + b * 8192 + kk * 32 + q * 4,
                 wb + (size_t)kk * 32 + q * 4);
        }
        CP_COMMIT();
    };

    // ===== Phase A: enc GEMM, A[32][64] = relu(enc @ w1), K=512 (4 chunks)
    const int h = tid & 63, g = tid >> 6;     // col, 4 row-groups x 8 rows
    float accA[8] = {0.f, 0.f, 0.f, 0.f, 0.f, 0.f, 0.f, 0.f};

    stage_enc(0, 0);
    for (int ch = 0; ch < 4; ch++) {
        const int b = ch & 1;
        if (ch + 1 < 4) { stage_enc(ch + 1, b ^ 1); CP_WAIT1(); }
        else            { CP_WAIT0(); }
        __syncthreads();

        const float* es = sD + b * 4096 + (g * 8) * 128;
        const float* ws = sW + b * 8192 + h;
#pragma unroll 2
        for (int kb = 0; kb < 128; kb += 4) {
            const float w0 = ws[(kb + 0) * 64], wv1 = ws[(kb + 1) * 64];
            const float w2 = ws[(kb + 2) * 64], w3  = ws[(kb + 3) * 64];
#pragma unroll
            for (int r = 0; r < 8; r++) {
                const float4 e = *(const float4*)(es + r * 128 + kb);
                accA[r] += e.x * w0;
                accA[r] += e.y * wv1;
                accA[r] += e.z * w2;
                accA[r] += e.w * w3;
            }
        }
        __syncthreads();
    }
#pragma unroll
    for (int r = 0; r < 8; r++)
        sAc[h * 33 + g * 8 + r] = fmaxf(accA[r], 0.f);

    // ===== Phase B: pol1, h1[32][32] = relu(mean @ pw1 + b1), K=1024 (8 ch)
    const int hc = tid & 31, g2 = tid >> 5;   // col, 8 row-groups x 4 rows
    float accB[4] = {0.f, 0.f, 0.f, 0.f};

    stage_pol(0, 0);
    for (int ch = 0; ch < 8; ch++) {
        const int b = ch & 1;
        if (ch + 1 < 8) { stage_pol(ch + 1, b ^ 1); CP_WAIT1(); }
        else            { CP_WAIT0(); }
        __syncthreads();

        const float* ms = sD + b * 4096 + (g2 * 4) * 128;
        const float* ws = sW + b * 8192 + hc;
#pragma unroll 2
        for (int kb = 0; kb < 128; kb += 4) {
            const float w0 = ws[(kb + 0) * 32], wv1 = ws[(kb + 1) * 32];
            const float w2 = ws[(kb + 2) * 32], w3  = ws[(kb + 3) * 32];
#pragma unroll
            for (int r = 0; r < 4; r++) {
                const float4 m4 = *(const float4*)(ms + r * 128 + kb);
                accB[r] += m4.x * w0;
                accB[r] += m4.y * wv1;
                accB[r] += m4.z * w2;
                accB[r] += m4.w * w3;
            }
        }
        __syncthreads();
    }
    {
        const float bb = pb1[hc];
#pragma unroll
        for (int r = 0; r < 4; r++)
            sH1[(g2 * 4 + r) * H_POL + hc] = fmaxf(accB[r] + bb, 0.f);
    }
    __syncthreads();

    // ===== pol2: h2 = relu(h1 @ pw2 + b2), K=32 (pw2 = 4KB, unrolled LDG)
    {
        float acc[4] = {0.f, 0.f, 0.f, 0.f};
#pragma unroll
        for (int k = 0; k < H_POL; k++) {
            const float w = pw2[k * H_POL + hc];
#pragma unroll
            for (int r = 0; r < 4; r++)
                acc[r] += sH1[(g2 * 4 + r) * H_POL + k] * w;
        }
        const float bb = pb2[hc];
#pragma unroll
        for (int r = 0; r < 4; r++)
            sAc[(64 + hc) * 33 + g2 * 4 + r] = fmaxf(acc[r] + bb, 0.f);
    }
    __syncthreads();

    // ===== write Acat transposed: g_Acat[feature][client] (coalesced)
    for (int i = tid; i < F_DIM * 32; i += 256) {
        const int r = i >> 5, m = i & 31;
        g_Acat[(size_t)r * NC + base + m] = sAc[r * 33 + m];
    }
}

// ---------------------------------------------------------------------------
// K2 v2: 32 clients/CTA, 512 threads (2 cols each), grid 512.
// f32x2 packed FMAs over client row-pairs; Wcat streamed once per CTA
// (halved L2 traffic vs 16-client tiles). FFMA2-pipe bound.
// ---------------------------------------------------------------------------
__global__ void __launch_bounds__(512, 1) k2_final(
    const float* __restrict__ eps,
    float* __restrict__ out_sample,
    float* __restrict__ out_logprob,
    float* __restrict__ out_entropy)
{
    __shared__ float aT[F_DIM * 32];          // 12 KB; reused as reduce buffer

    const int tid = threadIdx.x;
    const int m0  = blockIdx.x * 32;

#pragma unroll
    for (int t = 0; t < 6; t++) {
        const int i = tid + t * 512;
        const int r = i >> 5, m = i & 31;
        aT[i] = g_Acat[(size_t)r * NC + m0 + m];
    }
    __syncthreads();

    const int j0 = tid * 2;

    unsigned long long acc[16][2];
#pragma unroll
    for (int rp = 0; rp < 16; rp++) { acc[rp][0] = 0ull; acc[rp][1] = 0ull; }

#pragma unroll 4
    for (int r = 0; r < F_DIM; r++) {
        const float2 w = *(const float2*)(g_Wcat + r * P_DIM + j0);
        const unsigned long long wx = pack2(w.x, w.x);
        const unsigned long long wy = pack2(w.y, w.y);
#pragma unroll
        for (int rp = 0; rp < 16; rp++) {
            const unsigned long long a2 =
                *(const unsigned long long*)(aT + r * 32 + 2 * rp);
            fma2(acc[rp][0], a2, wx);
            fma2(acc[rp][1], a2, wy);
        }
    }
    __syncthreads();   // before reusing aT as reduction scratch

    const float2 b2  = *(const float2*)(g_Wcat + F_DIM * P_DIM + j0);
    const int wid  = tid >> 5;
    const int lane = tid & 31;

#pragma unroll
    for (int rp = 0; rp < 16; rp++) {
        const float2 zx = unpack2(acc[rp][0]);   // rows (2rp, 2rp+1), col j0
        const float2 zy = unpack2(acc[rp][1]);   // rows (2rp, 2rp+1), col j0+1
#pragma unroll
        for (int hh = 0; hh < 2; hh++) {
            const int row = 2 * rp + hh;
            const float z0 = (hh ? zx.y : zx.x) + b2.x;
            const float z1 = (hh ? zy.y : zy.x) + b2.y;

            const float2 e2 =
                *(const float2*)(eps + (size_t)(m0 + row) * P_DIM + j0);

            const float mv0 = __fdividef(1.f, 1.f + __expf(-z0));
            const float mv1 = __fdividef(1.f, 1.f + __expf(-z1));
            const float s0 = fminf(fmaxf(mv0 + SQRT_VAR * e2.x, 0.f), 1.f);
            const float s1 = fminf(fmaxf(mv1 + SQRT_VAR * e2.y, 0.f), 1.f);

            float2 o; o.x = s0; o.y = s1;
            *(float2*)(out_sample + (size_t)(m0 + row) * P_DIM + j0) = o;

            const float d0 = s0 - mv0, d1 = s1 - mv1;
            float ss = d0 * d0 + d1 * d1;
#pragma unroll
            for (int off = 16; off; off >>= 1)
                ss += __shfl_xor_sync(0xffffffffu, ss, off);
            if (lane == 0) aT[row * 16 + wid] = ss;
        }
    }
    __syncthreads();

    if (tid < 32) {
        float s = 0.f;
#pragma unroll
        for (int w = 0; w < 16; w++) s += aT[tid * 16 + w];
        out_logprob[m0 + tid] = -10.0f * s + LOGPROB_CONST;   // -0.5/VAR
        out_entropy[m0 + tid] = ENTROPY_CONST;
    }
}

// ---------------------------------------------------------------------------
extern "C" void kernel_launch(void* const* d_in, const int* in_sizes, int n_in,
                              void* d_out, int out_size) {
    const float* encoding = (const float*)d_in[0];
    const float* mean     = (const float*)d_in[1];
    const float* enc_w1   = (const float*)d_in[2];
    const float* enc_w2   = (const float*)d_in[3];
    const float* pol_w1   = (const float*)d_in[4];
    const float* pol_b1   = (const float*)d_in[5];
    const float* pol_w2   = (const float*)d_in[6];
    const float* pol_b2   = (const float*)d_in[7];
    const float* pol_w3   = (const float*)d_in[8];
    const float* pol_b3   = (const float*)d_in[9];
    const float* comb_w   = (const float*)d_in[10];
    const float* comb_b   = (const float*)d_in[11];
    const float* eps      = (const float*)d_in[12];

    float* out         = (float*)d_out;
    float* out_sample  = out;                              // [N, 1024]
    float* out_logprob = out + (size_t)NC * P_DIM;         // [N]
    float* out_entropy = out_logprob + NC;                 // [N]

    cudaFuncSetAttribute(k1_acat,
                         cudaFuncAttributeMaxDynamicSharedMemorySize,
                         K1_BYTES);

    k0_fold<<<dim3(8, 13), 128>>>(enc_w2, pol_w3, pol_b3, comb_w, comb_b);
    k1_acat<<<NC / 32, 256, K1_BYTES>>>(encoding, mean, enc_w1,
                                        pol_w1, pol_b1, pol_w2, pol_b2);
    k2_final<<<NC / 32, 512>>>(eps, out_sample, out_logprob, out_entropy);
}